// round 9
// baseline (speedup 1.0000x reference)
#include <cuda_runtime.h>
#include <cstdint>

#define HID 4096
#define NHEADS 32
#define NKV 8
#define HD 128
#define BATCH 2
#define SEQ 2048
#define TOK (BATCH*SEQ)
#define KVDIM (NKV*HD)
#define INV_SQRT_D 0.08838834764831845f

// ---------------- device-global scratch (no allocations allowed) ----------------
__device__ int8_t g_xq [(size_t)TOK*HID];
__device__ int8_t g_xq2[(size_t)TOK*HID];
__device__ float  g_xscale [TOK];
__device__ float  g_xscale2[TOK];
__device__ int8_t g_Wq8[(size_t)HID*HID];
__device__ int8_t g_Wk8[(size_t)KVDIM*HID];
__device__ int8_t g_Wv8[(size_t)KVDIM*HID];
__device__ int8_t g_Wo8[(size_t)HID*HID];
__device__ float  g_partial[4][1024];
__device__ float  g_wscale[4];
__device__ float  g_Q[(size_t)BATCH*NHEADS*SEQ*HD];
__device__ float  g_K[(size_t)BATCH*NKV*SEQ*HD];
__device__ float  g_V[(size_t)BATCH*NKV*SEQ*HD];
__device__ float  g_attn[(size_t)TOK*HID];

// ---------------- weight |.| partial sums (deterministic two-stage) ----------------
__global__ void k_wabs(const float* __restrict__ W, int n4, int mid) {
    float s = 0.f;
    const float4* W4 = (const float4*)W;
    for (int i = blockIdx.x * blockDim.x + threadIdx.x; i < n4; i += gridDim.x * blockDim.x) {
        float4 v = W4[i];
        s += fabsf(v.x) + fabsf(v.y) + fabsf(v.z) + fabsf(v.w);
    }
    __shared__ float red[256];
    red[threadIdx.x] = s;
    __syncthreads();
    for (int o = 128; o > 0; o >>= 1) {
        if (threadIdx.x < o) red[threadIdx.x] += red[threadIdx.x + o];
        __syncthreads();
    }
    if (threadIdx.x == 0) g_partial[mid][blockIdx.x] = red[0];
}

__global__ void k_wscale() {
    int mid = blockIdx.x;
    int tid = threadIdx.x;
    float s = 0.f;
    for (int i = tid; i < 1024; i += 256) s += g_partial[mid][i];
    __shared__ float red[256];
    red[tid] = s;
    __syncthreads();
    for (int o = 128; o > 0; o >>= 1) {
        if (tid < o) red[tid] += red[tid + o];
        __syncthreads();
    }
    if (tid == 0) {
        float n = (mid == 1 || mid == 2) ? (float)((size_t)KVDIM * HID) : (float)((size_t)HID * HID);
        g_wscale[mid] = fmaxf(red[0] / n, 1e-5f);
    }
}

// ---------------- ternary weight quantization ----------------
__global__ void k_quantw(const float* __restrict__ Wq, const float* __restrict__ Wk,
                         const float* __restrict__ Wv, const float* __restrict__ Wo) {
    int mid = blockIdx.y;
    const float* W = mid == 0 ? Wq : mid == 1 ? Wk : mid == 2 ? Wv : Wo;
    int8_t* out = mid == 0 ? g_Wq8 : mid == 1 ? g_Wk8 : mid == 2 ? g_Wv8 : g_Wo8;
    int n4 = (mid == 1 || mid == 2) ? (KVDIM * HID / 4) : (HID * HID / 4);
    float inv = 1.0f / g_wscale[mid];
    const float4* W4 = (const float4*)W;
    char4* o4 = (char4*)out;
    for (int i = blockIdx.x * 256 + threadIdx.x; i < n4; i += gridDim.x * 256) {
        float4 v = W4[i];
        char4 c;
        c.x = (signed char)max(-1, min(1, __float2int_rn(v.x * inv)));
        c.y = (signed char)max(-1, min(1, __float2int_rn(v.y * inv)));
        c.z = (signed char)max(-1, min(1, __float2int_rn(v.z * inv)));
        c.w = (signed char)max(-1, min(1, __float2int_rn(v.w * inv)));
        o4[i] = c;
    }
}

// ---------------- per-token activation int8 quantization ----------------
__global__ void k_actq(const float* __restrict__ xin, int which) {
    const float* x = which ? (const float*)g_attn : xin;
    int8_t* xq = which ? g_xq2 : g_xq;
    float* xs = which ? g_xscale2 : g_xscale;
    int t = blockIdx.x;
    int tid = threadIdx.x;
    const float4* row = (const float4*)(x + (size_t)t * HID);
    float4 v[4];
    float mx = 0.f;
#pragma unroll
    for (int i = 0; i < 4; i++) {
        v[i] = row[tid + i * 256];
        mx = fmaxf(mx, fmaxf(fmaxf(fabsf(v[i].x), fabsf(v[i].y)), fmaxf(fabsf(v[i].z), fabsf(v[i].w))));
    }
    __shared__ float red[256];
    red[tid] = mx;
    __syncthreads();
    for (int o = 128; o > 0; o >>= 1) {
        if (tid < o) red[tid] = fmaxf(red[tid], red[tid + o]);
        __syncthreads();
    }
    float amax = fmaxf(red[0], 1e-5f);
    float sc = 127.0f / amax;
    if (tid == 0) xs[t] = amax * (1.0f / 127.0f);
    char4* oq = (char4*)(xq + (size_t)t * HID);
#pragma unroll
    for (int i = 0; i < 4; i++) {
        char4 c;
        c.x = (signed char)max(-128, min(127, __float2int_rn(v[i].x * sc)));
        c.y = (signed char)max(-128, min(127, __float2int_rn(v[i].y * sc)));
        c.z = (signed char)max(-128, min(127, __float2int_rn(v[i].z * sc)));
        c.w = (signed char)max(-128, min(127, __float2int_rn(v[i].w * sc)));
        oq[tid + i * 256] = c;
    }
}

// ---------------- int8 tensor-core GEMM (mma.sync m16n8k32 s8) ----------------
__device__ __forceinline__ void mma16832(int* d, int a0, int a1, int a2, int a3, int b0, int b1) {
    asm volatile("mma.sync.aligned.m16n8k32.row.col.s32.s8.s8.s32 "
                 "{%0,%1,%2,%3}, {%4,%5,%6,%7}, {%8,%9}, {%0,%1,%2,%3};"
                 : "+r"(d[0]), "+r"(d[1]), "+r"(d[2]), "+r"(d[3])
                 : "r"(a0), "r"(a1), "r"(a2), "r"(a3), "r"(b0), "r"(b1));
}
__device__ __forceinline__ void cp16(unsigned dst, const void* src) {
    asm volatile("cp.async.cg.shared.global [%0], [%1], 16;" :: "r"(dst), "l"(src));
}

// Block 128x128, K-chunks of 64B, 3-stage cp.async pipeline, 4 warps (2x2, 64x64 tiles).
// Smem is XOR-swizzled in 16B units: unit' = unit ^ (row&3) -> all LDS.128 conflict-free.
// k-order inside each 64B chunk is freely permuted identically for A and B fragments.
__global__ __launch_bounds__(128, 2) void k_gemm_imma(int wmid, int aid, float* __restrict__ oext,
                                                      int nh, int mode) {
    const int8_t* __restrict__ Wt = wmid == 0 ? g_Wq8 : wmid == 1 ? g_Wk8 : wmid == 2 ? g_Wv8 : g_Wo8;
    const int8_t* __restrict__ A = aid ? g_xq2 : g_xq;
    const float* __restrict__ asc = aid ? g_xscale2 : g_xscale;
    float* outp = (mode == 0) ? (wmid == 0 ? g_Q : (wmid == 1 ? g_K : g_V)) : oext;

    const int n0 = blockIdx.x * 128;
    const int m0 = blockIdx.y * 128;

    __shared__ int8_t As[3][128 * 64];
    __shared__ int8_t Bs[3][128 * 64];

    const int tid = threadIdx.x;
    const int lane = tid & 31, warp = tid >> 5;
    const int wm = (warp >> 1) * 64, wn = (warp & 1) * 64;
    const int gid = lane >> 2, tig = lane & 3;

    int d[4][8][4];
#pragma unroll
    for (int mt = 0; mt < 4; mt++)
#pragma unroll
        for (int nt = 0; nt < 8; nt++)
#pragma unroll
            for (int i = 0; i < 4; i++) d[mt][nt][i] = 0;

    // stage loader: 512 16B units for A and B each; 4 per thread each
#define STAGE_LOAD(buf, k0)                                                             \
    {                                                                                   \
        _Pragma("unroll")                                                               \
        for (int i = 0; i < 4; i++) {                                                   \
            int u = i * 128 + tid;                                                      \
            int r = u >> 2, cu = u & 3;                                                 \
            int sw = r * 64 + ((cu ^ (r & 3)) << 4);                                    \
            cp16((unsigned)__cvta_generic_to_shared(&As[buf][sw]),                      \
                 A + (size_t)(m0 + r) * HID + (k0) + cu * 16);                          \
            cp16((unsigned)__cvta_generic_to_shared(&Bs[buf][sw]),                      \
                 Wt + (size_t)(n0 + r) * HID + (k0) + cu * 16);                         \
        }                                                                               \
        asm volatile("cp.async.commit_group;");                                         \
    }

    STAGE_LOAD(0, 0);
    STAGE_LOAD(1, 64);

    const int NK = HID / 64;  // 64
    int buf = 0;
#pragma unroll 1
    for (int kt = 0; kt < NK; kt++) {
        if (kt + 2 < NK) {
            int nb = buf + 2; if (nb >= 3) nb -= 3;
            STAGE_LOAD(nb, (kt + 2) * 64);
            asm volatile("cp.async.wait_group 2;");
        } else if (kt + 1 < NK) {
            asm volatile("cp.async.wait_group 1;");
        } else {
            asm volatile("cp.async.wait_group 0;");
        }
        __syncthreads();

        const int8_t* Ab = As[buf];
        const int8_t* Bb = Bs[buf];

        // A fragments: per m-tile, rows (base+gid) and (base+gid+8), 16B each
        int a[4][8];
#pragma unroll
        for (int mt = 0; mt < 4; mt++) {
            int r = wm + mt * 16 + gid;
            int4 lo = *(const int4*)(Ab + r * 64 + ((tig ^ (r & 3)) << 4));
            int r2 = r + 8;
            int4 hi = *(const int4*)(Ab + r2 * 64 + ((tig ^ (r2 & 3)) << 4));
            a[mt][0] = lo.x; a[mt][1] = lo.y; a[mt][2] = lo.z; a[mt][3] = lo.w;
            a[mt][4] = hi.x; a[mt][5] = hi.y; a[mt][6] = hi.z; a[mt][7] = hi.w;
        }
#pragma unroll
        for (int nt = 0; nt < 8; nt++) {
            int rb = wn + nt * 8 + gid;
            int4 bv = *(const int4*)(Bb + rb * 64 + ((tig ^ (rb & 3)) << 4));
#pragma unroll
            for (int mt = 0; mt < 4; mt++) {
                mma16832(d[mt][nt], a[mt][0], a[mt][4], a[mt][1], a[mt][5], bv.x, bv.y);
                mma16832(d[mt][nt], a[mt][2], a[mt][6], a[mt][3], a[mt][7], bv.z, bv.w);
            }
        }
        __syncthreads();
        buf++; if (buf >= 3) buf -= 3;
    }
#undef STAGE_LOAD

    // epilogue: scale by wscale * per-token ascale, write float2
    float ws = g_wscale[wmid];
#pragma unroll
    for (int mt = 0; mt < 4; mt++) {
#pragma unroll
        for (int half = 0; half < 2; half++) {
            int m = m0 + wm + mt * 16 + gid + 8 * half;
            float sc = ws * asc[m];
            float* dst;
            if (mode == 0) {
                int bidx = m >> 11, sidx = m & (SEQ - 1);
                int hh = n0 >> 7;  // 128-wide tiles align with head boundaries
                dst = outp + (((size_t)bidx * nh + hh) * SEQ + sidx) * HD;
            } else {
                dst = outp + (size_t)m * HID + n0;
            }
#pragma unroll
            for (int nt = 0; nt < 8; nt++) {
                int n = wn + nt * 8 + 2 * tig;
                float2 w;
                w.x = (float)d[mt][nt][2 * half] * sc;
                w.y = (float)d[mt][nt][2 * half + 1] * sc;
                *(float2*)(dst + n) = w;
            }
        }
    }
}

// ---------------- causal flash attention, base-2 online softmax ----------------
// grid (32 q-tiles [reversed], 32 heads, 2 batch), 256 threads.
// smem: Qs[64][132] | Ks[64][132] (reused as Ps[64][68]) | Vs[64][128]
__global__ __launch_bounds__(256) void k_attn() {
    extern __shared__ float sm[];
    float* Qs = sm;
    float* Ks = sm + 64 * 132;
    float* Ps = Ks;                       // reused after S is computed
    float* Vs = sm + 2 * 64 * 132;
    const int qt = 31 - (int)blockIdx.x;  // heavy tiles first
    const int h = blockIdx.y;
    const int b = blockIdx.z;
    const int tid = threadIdx.x;
    const int tx = tid & 15, ty = tid >> 4;
    const int r0 = ty * 4;

    const float* Qg = g_Q + (((size_t)b * NHEADS + h) * SEQ + (size_t)qt * 64) * HD;
    const float* Kg = g_K + ((size_t)b * NKV + (h >> 2)) * SEQ * HD;
    const float* Vg = g_V + ((size_t)b * NKV + (h >> 2)) * SEQ * HD;

    {   // load Q tile pre-scaled by 1/sqrt(D)
        const float4* Qg4 = (const float4*)Qg;
        for (int i = tid; i < 64 * 32; i += 256) {
            float4 v = Qg4[i];
            v.x *= INV_SQRT_D; v.y *= INV_SQRT_D; v.z *= INV_SQRT_D; v.w *= INV_SQRT_D;
            int row = i >> 5, d4 = i & 31;
            *(float4*)&Qs[row * 132 + d4 * 4] = v;
        }
    }

    float m_i[4], l_i[4], o_acc[4][8];
#pragma unroll
    for (int i = 0; i < 4; i++) {
        m_i[i] = -1e30f; l_i[i] = 0.f;
#pragma unroll
        for (int j = 0; j < 8; j++) o_acc[i][j] = 0.f;
    }

    for (int kt = 0; kt <= qt; kt++) {
        __syncthreads();  // previous PV done before overwriting K/V/P
        const float4* Kg4 = (const float4*)(Kg + (size_t)kt * 64 * HD);
        const float4* Vg4 = (const float4*)(Vg + (size_t)kt * 64 * HD);
        for (int i = tid; i < 64 * 32; i += 256) {
            int row = i >> 5, d4 = i & 31;
            *(float4*)&Ks[row * 132 + d4 * 4] = Kg4[i];
            *(float4*)&Vs[row * 128 + d4 * 4] = Vg4[i];
        }
        __syncthreads();

        // ---- S = Q K^T : rows r0..r0+3, cols j*16+tx ----
        float acc[4][4];
#pragma unroll
        for (int i = 0; i < 4; i++)
#pragma unroll
            for (int j = 0; j < 4; j++) acc[i][j] = 0.f;
#pragma unroll 4
        for (int d4 = 0; d4 < 32; d4++) {
            float4 a[4], bb[4];
#pragma unroll
            for (int i = 0; i < 4; i++) a[i] = *(const float4*)&Qs[(r0 + i) * 132 + d4 * 4];
#pragma unroll
            for (int j = 0; j < 4; j++) bb[j] = *(const float4*)&Ks[(j * 16 + tx) * 132 + d4 * 4];
#pragma unroll
            for (int i = 0; i < 4; i++)
#pragma unroll
                for (int j = 0; j < 4; j++) {
                    acc[i][j] += a[i].x * bb[j].x;
                    acc[i][j] += a[i].y * bb[j].y;
                    acc[i][j] += a[i].z * bb[j].z;
                    acc[i][j] += a[i].w * bb[j].w;
                }
        }
        if (kt == qt) {  // diagonal tile: causal mask
#pragma unroll
            for (int i = 0; i < 4; i++) {
                int rg = qt * 64 + r0 + i;
#pragma unroll
                for (int j = 0; j < 4; j++) {
                    int cg = kt * 64 + j * 16 + tx;
                    if (cg > rg) acc[i][j] = -1e30f;
                }
            }
        }
        __syncthreads();  // all Ks reads done before Ps overwrite

        // ---- online base-2 softmax update, P into shared ----
#pragma unroll
        for (int i = 0; i < 4; i++) {
            float rm = fmaxf(fmaxf(acc[i][0], acc[i][1]), fmaxf(acc[i][2], acc[i][3]));
#pragma unroll
            for (int o = 8; o > 0; o >>= 1)
                rm = fmaxf(rm, __shfl_xor_sync(0xffffffffu, rm, o, 16));
            float m_new = fmaxf(m_i[i], rm);
            float scale = exp2f(m_i[i] - m_new);
            float p[4], rs = 0.f;
#pragma unroll
            for (int j = 0; j < 4; j++) { p[j] = exp2f(acc[i][j] - m_new); rs += p[j]; }
#pragma unroll
            for (int o = 8; o > 0; o >>= 1)
                rs += __shfl_xor_sync(0xffffffffu, rs, o, 16);
            l_i[i] = l_i[i] * scale + rs;
            m_i[i] = m_new;
#pragma unroll
            for (int j = 0; j < 8; j++) o_acc[i][j] *= scale;
#pragma unroll
            for (int j = 0; j < 4; j++) Ps[(r0 + i) * 68 + j * 16 + tx] = p[j];
        }
        __syncthreads();  // Ps visible to all

        // ---- O += P V : thread owns d = tx*8..tx*8+7 ----
#pragma unroll 2
        for (int c = 0; c < 64; c++) {
            float pv[4];
#pragma unroll
            for (int i = 0; i < 4; i++) pv[i] = Ps[(r0 + i) * 68 + c];
            float4 v0 = *(const float4*)&Vs[c * 128 + tx * 8];
            float4 v1 = *(const float4*)&Vs[c * 128 + tx * 8 + 4];
#pragma unroll
            for (int i = 0; i < 4; i++) {
                o_acc[i][0] += pv[i] * v0.x; o_acc[i][1] += pv[i] * v0.y;
                o_acc[i][2] += pv[i] * v0.z; o_acc[i][3] += pv[i] * v0.w;
                o_acc[i][4] += pv[i] * v1.x; o_acc[i][5] += pv[i] * v1.y;
                o_acc[i][6] += pv[i] * v1.z; o_acc[i][7] += pv[i] * v1.w;
            }
        }
    }

    // ---- normalize + write (token-major into g_attn) ----
#pragma unroll
    for (int i = 0; i < 4; i++) {
        float inv_l = 1.0f / l_i[i];
        int sg = qt * 64 + r0 + i;
        float* dst = g_attn + ((size_t)(b * SEQ + sg)) * HID + h * HD + tx * 8;
        float4 w0, w1;
        w0.x = o_acc[i][0] * inv_l; w0.y = o_acc[i][1] * inv_l;
        w0.z = o_acc[i][2] * inv_l; w0.w = o_acc[i][3] * inv_l;
        w1.x = o_acc[i][4] * inv_l; w1.y = o_acc[i][5] * inv_l;
        w1.z = o_acc[i][6] * inv_l; w1.w = o_acc[i][7] * inv_l;
        *(float4*)dst = w0;
        *(float4*)(dst + 4) = w1;
    }
}

// ---------------- launcher ----------------
extern "C" void kernel_launch(void* const* d_in, const int* in_sizes, int n_in,
                              void* d_out, int out_size) {
    const float* hidden = (const float*)d_in[0];
    // d_in[1] is the attention mask: causal additive mask; handled analytically.
    const float* Wq = (const float*)d_in[2];
    const float* Wk = (const float*)d_in[3];
    const float* Wv = (const float*)d_in[4];
    const float* Wo = (const float*)d_in[5];
    float* out = (float*)d_out;

    const int SMEM_ATTN = (2 * 64 * 132 + 64 * 128) * (int)sizeof(float);
    cudaFuncSetAttribute(k_attn, cudaFuncAttributeMaxDynamicSharedMemorySize, SMEM_ATTN);

    // weight scales (mean |W|)
    k_wabs<<<1024, 256>>>(Wq, HID * HID / 4, 0);
    k_wabs<<<1024, 256>>>(Wk, KVDIM * HID / 4, 1);
    k_wabs<<<1024, 256>>>(Wv, KVDIM * HID / 4, 2);
    k_wabs<<<1024, 256>>>(Wo, HID * HID / 4, 3);
    k_wscale<<<4, 256>>>();

    // quantize weights (ternary) and activations (int8 per token)
    k_quantw<<<dim3(2048, 4), 256>>>(Wq, Wk, Wv, Wo);
    k_actq<<<TOK, 256>>>(hidden, 0);

    // projections (int8 tensor cores)
    k_gemm_imma<<<dim3(HID / 128, TOK / 128), 128>>>(0, 0, nullptr, NHEADS, 0);   // Q
    k_gemm_imma<<<dim3(KVDIM / 128, TOK / 128), 128>>>(1, 0, nullptr, NKV, 0);    // K
    k_gemm_imma<<<dim3(KVDIM / 128, TOK / 128), 128>>>(2, 0, nullptr, NKV, 0);    // V

    // attention
    k_attn<<<dim3(SEQ / 64, NHEADS, BATCH), 256, SMEM_ATTN>>>();

    // output projection
    k_actq<<<TOK, 256>>>(nullptr, 1);
    k_gemm_imma<<<dim3(HID / 128, TOK / 128), 128>>>(3, 1, out, NHEADS, 1);       // O
}

// round 16
// speedup vs baseline: 2.1935x; 2.1935x over previous
#include <cuda_runtime.h>
#include <cuda_bf16.h>
#include <cstdint>

#define HID 4096
#define NHEADS 32
#define NKV 8
#define HD 128
#define BATCH 2
#define SEQ 2048
#define TOK (BATCH*SEQ)
#define KVDIM (NKV*HD)
#define INV_SQRT_D 0.08838834764831845f

// ---------------- device-global scratch (no allocations allowed) ----------------
__device__ __nv_bfloat16 g_xb [(size_t)TOK*HID];
__device__ __nv_bfloat16 g_xb2[(size_t)TOK*HID];
__device__ float  g_xscale [TOK];
__device__ float  g_xscale2[TOK];
__device__ __nv_bfloat16 g_Wqb[(size_t)HID*HID];
__device__ __nv_bfloat16 g_Wkb[(size_t)KVDIM*HID];
__device__ __nv_bfloat16 g_Wvb[(size_t)KVDIM*HID];
__device__ __nv_bfloat16 g_Wob[(size_t)HID*HID];
__device__ float  g_partial[4][1024];
__device__ float  g_wscale[4];
__device__ float  g_Q[(size_t)BATCH*NHEADS*SEQ*HD];
__device__ float  g_K[(size_t)BATCH*NKV*SEQ*HD];
__device__ float  g_V[(size_t)BATCH*NKV*SEQ*HD];
__device__ float  g_attn[(size_t)TOK*HID];

// ---------------- packed f32x2 helpers (sm_100 baseline, not 'a'-gated) ----------------
__device__ __forceinline__ unsigned long long pack2(float lo, float hi) {
    unsigned long long r;
    asm("mov.b64 %0, {%1,%2};" : "=l"(r) : "f"(lo), "f"(hi));
    return r;
}
__device__ __forceinline__ void unpack2(unsigned long long v, float& lo, float& hi) {
    asm("mov.b64 {%0,%1}, %2;" : "=f"(lo), "=f"(hi) : "l"(v));
}
__device__ __forceinline__ void ffma2(unsigned long long& d, unsigned long long a, unsigned long long b) {
    asm("fma.rn.f32x2 %0, %1, %2, %0;" : "+l"(d) : "l"(a), "l"(b));
}
__device__ __forceinline__ void fmul2(unsigned long long& d, unsigned long long a, unsigned long long b) {
    asm("mul.rn.f32x2 %0, %1, %2;" : "=l"(d) : "l"(a), "l"(b));
}

// ---------------- bf16 HMMA + cp.async ----------------
__device__ __forceinline__ void mma_bf16(float* d, uint32_t a0, uint32_t a1, uint32_t a2, uint32_t a3,
                                         uint32_t b0, uint32_t b1) {
    asm volatile("mma.sync.aligned.m16n8k16.row.col.f32.bf16.bf16.f32 "
                 "{%0,%1,%2,%3}, {%4,%5,%6,%7}, {%8,%9}, {%0,%1,%2,%3};"
                 : "+f"(d[0]), "+f"(d[1]), "+f"(d[2]), "+f"(d[3])
                 : "r"(a0), "r"(a1), "r"(a2), "r"(a3), "r"(b0), "r"(b1));
}
__device__ __forceinline__ void cp16(unsigned dst, const void* src) {
    asm volatile("cp.async.cg.shared.global [%0], [%1], 16;" :: "r"(dst), "l"(src));
}

// ---------------- weight |.| partial sums (deterministic two-stage) ----------------
__global__ void k_wabs(const float* __restrict__ W, int n4, int mid) {
    float s = 0.f;
    const float4* W4 = (const float4*)W;
    for (int i = blockIdx.x * blockDim.x + threadIdx.x; i < n4; i += gridDim.x * blockDim.x) {
        float4 v = W4[i];
        s += fabsf(v.x) + fabsf(v.y) + fabsf(v.z) + fabsf(v.w);
    }
    __shared__ float red[256];
    red[threadIdx.x] = s;
    __syncthreads();
    for (int o = 128; o > 0; o >>= 1) {
        if (threadIdx.x < o) red[threadIdx.x] += red[threadIdx.x + o];
        __syncthreads();
    }
    if (threadIdx.x == 0) g_partial[mid][blockIdx.x] = red[0];
}

__global__ void k_wscale() {
    int mid = blockIdx.x;
    int tid = threadIdx.x;
    float s = 0.f;
    for (int i = tid; i < 1024; i += 256) s += g_partial[mid][i];
    __shared__ float red[256];
    red[tid] = s;
    __syncthreads();
    for (int o = 128; o > 0; o >>= 1) {
        if (tid < o) red[tid] += red[tid + o];
        __syncthreads();
    }
    if (tid == 0) {
        float n = (mid == 1 || mid == 2) ? (float)((size_t)KVDIM * HID) : (float)((size_t)HID * HID);
        g_wscale[mid] = fmaxf(red[0] / n, 1e-5f);
    }
}

// ---------------- ternary weight quantization -> bf16 (exact) ----------------
__global__ void k_quantw(const float* __restrict__ Wq, const float* __restrict__ Wk,
                         const float* __restrict__ Wv, const float* __restrict__ Wo) {
    int mid = blockIdx.y;
    const float* W = mid == 0 ? Wq : mid == 1 ? Wk : mid == 2 ? Wv : Wo;
    __nv_bfloat16* out = mid == 0 ? g_Wqb : mid == 1 ? g_Wkb : mid == 2 ? g_Wvb : g_Wob;
    int n4 = (mid == 1 || mid == 2) ? (KVDIM * HID / 4) : (HID * HID / 4);
    float inv = 1.0f / g_wscale[mid];
    const float4* W4 = (const float4*)W;
    for (int i = blockIdx.x * 256 + threadIdx.x; i < n4; i += gridDim.x * 256) {
        float4 v = W4[i];
        float c0 = fminf(fmaxf(rintf(v.x * inv), -1.f), 1.f);
        float c1 = fminf(fmaxf(rintf(v.y * inv), -1.f), 1.f);
        float c2 = fminf(fmaxf(rintf(v.z * inv), -1.f), 1.f);
        float c3 = fminf(fmaxf(rintf(v.w * inv), -1.f), 1.f);
        __nv_bfloat162* o2 = (__nv_bfloat162*)(out + (size_t)i * 4);
        o2[0] = __floats2bfloat162_rn(c0, c1);
        o2[1] = __floats2bfloat162_rn(c2, c3);
    }
}

// ---------------- per-token activation int8 quantization -> bf16 (exact) ----------------
__global__ void k_actq(const float* __restrict__ xin, int which) {
    const float* x = which ? (const float*)g_attn : xin;
    __nv_bfloat16* xq = which ? g_xb2 : g_xb;
    float* xs = which ? g_xscale2 : g_xscale;
    int t = blockIdx.x;
    int tid = threadIdx.x;
    const float4* row = (const float4*)(x + (size_t)t * HID);
    float4 v[4];
    float mx = 0.f;
#pragma unroll
    for (int i = 0; i < 4; i++) {
        v[i] = row[tid + i * 256];
        mx = fmaxf(mx, fmaxf(fmaxf(fabsf(v[i].x), fabsf(v[i].y)), fmaxf(fabsf(v[i].z), fabsf(v[i].w))));
    }
    __shared__ float red[256];
    red[tid] = mx;
    __syncthreads();
    for (int o = 128; o > 0; o >>= 1) {
        if (tid < o) red[tid] = fmaxf(red[tid], red[tid + o]);
        __syncthreads();
    }
    float amax = fmaxf(red[0], 1e-5f);
    float sc = 127.0f / amax;
    if (tid == 0) xs[t] = amax * (1.0f / 127.0f);
    __nv_bfloat162* oq = (__nv_bfloat162*)(xq + (size_t)t * HID);
#pragma unroll
    for (int i = 0; i < 4; i++) {
        int j = tid + i * 256;
        float c0 = fminf(fmaxf(rintf(v[i].x * sc), -128.f), 127.f);
        float c1 = fminf(fmaxf(rintf(v[i].y * sc), -128.f), 127.f);
        float c2 = fminf(fmaxf(rintf(v[i].z * sc), -128.f), 127.f);
        float c3 = fminf(fmaxf(rintf(v[i].w * sc), -128.f), 127.f);
        oq[2 * j]     = __floats2bfloat162_rn(c0, c1);
        oq[2 * j + 1] = __floats2bfloat162_rn(c2, c3);
    }
}

// ---------------- bf16 HMMA GEMM: C[m,n] = (ws*asc[m]) * sum_k A[m,k]*W[n,k] ----------------
// Block 128x128, K-chunks of 32 bf16 (64B/row), 3-stage cp.async, 4 warps (2x2 of 64x64).
// Smem XOR-swizzled in 16B units (unit' = unit ^ (row&3)); k-order permuted identically
// for A and B fragments so one LDS.128 per row feeds two m16n8k16 MMAs.
// mode 0: write head-major [b][head][s][d]; mode 1: token-major [token][n].
__global__ __launch_bounds__(128, 2) void k_gemm_hmma(int wmid, int aid, float* __restrict__ oext,
                                                      int nh, int mode) {
    const __nv_bfloat16* __restrict__ Wt = wmid == 0 ? g_Wqb : wmid == 1 ? g_Wkb : wmid == 2 ? g_Wvb : g_Wob;
    const __nv_bfloat16* __restrict__ A = aid ? g_xb2 : g_xb;
    const float* __restrict__ asc = aid ? g_xscale2 : g_xscale;
    float* outp = (mode == 0) ? (wmid == 0 ? g_Q : (wmid == 1 ? g_K : g_V)) : oext;

    const int n0 = blockIdx.x * 128;
    const int m0 = blockIdx.y * 128;

    __shared__ __align__(16) int8_t As[3][128 * 64];
    __shared__ __align__(16) int8_t Bs[3][128 * 64];

    const int tid = threadIdx.x;
    const int lane = tid & 31, warp = tid >> 5;
    const int wm = (warp >> 1) * 64, wn = (warp & 1) * 64;
    const int gid = lane >> 2, tig = lane & 3;

    float d[4][8][4];
#pragma unroll
    for (int mt = 0; mt < 4; mt++)
#pragma unroll
        for (int nt = 0; nt < 8; nt++)
#pragma unroll
            for (int i = 0; i < 4; i++) d[mt][nt][i] = 0.f;

    // stage loader: 512 16B units per matrix (128 rows x 4 units); 4 per thread each
#define STAGE_LOAD(buf, k0)                                                             \
    {                                                                                   \
        _Pragma("unroll")                                                               \
        for (int i = 0; i < 4; i++) {                                                   \
            int u = i * 128 + tid;                                                      \
            int r = u >> 2, cu = u & 3;                                                 \
            int sw = r * 64 + ((cu ^ (r & 3)) << 4);                                    \
            cp16((unsigned)__cvta_generic_to_shared(&As[buf][sw]),                      \
                 A + (size_t)(m0 + r) * HID + (k0) + cu * 8);                           \
            cp16((unsigned)__cvta_generic_to_shared(&Bs[buf][sw]),                      \
                 Wt + (size_t)(n0 + r) * HID + (k0) + cu * 8);                          \
        }                                                                               \
        asm volatile("cp.async.commit_group;");                                         \
    }

    STAGE_LOAD(0, 0);
    STAGE_LOAD(1, 32);

    const int NK = HID / 32;  // 128 chunks
    int buf = 0;
#pragma unroll 1
    for (int kt = 0; kt < NK; kt++) {
        if (kt + 2 < NK) {
            int nb = buf + 2; if (nb >= 3) nb -= 3;
            STAGE_LOAD(nb, (kt + 2) * 32);
            asm volatile("cp.async.wait_group 2;");
        } else if (kt + 1 < NK) {
            asm volatile("cp.async.wait_group 1;");
        } else {
            asm volatile("cp.async.wait_group 0;");
        }
        __syncthreads();

        const int8_t* Ab = As[buf];
        const int8_t* Bb = Bs[buf];

        // A fragments: per m-tile, rows (base+gid) and (base+gid+8), 16B each
        uint4 alo[4], ahi[4];
#pragma unroll
        for (int mt = 0; mt < 4; mt++) {
            int r = wm + mt * 16 + gid;
            alo[mt] = *(const uint4*)(Ab + r * 64 + ((tig ^ (r & 3)) << 4));
            int r2 = r + 8;
            ahi[mt] = *(const uint4*)(Ab + r2 * 64 + ((tig ^ (r2 & 3)) << 4));
        }
#pragma unroll
        for (int nt = 0; nt < 8; nt++) {
            int rb = wn + nt * 8 + gid;
            uint4 bv = *(const uint4*)(Bb + rb * 64 + ((tig ^ (rb & 3)) << 4));
#pragma unroll
            for (int mt = 0; mt < 4; mt++) {
                mma_bf16(d[mt][nt], alo[mt].x, ahi[mt].x, alo[mt].y, ahi[mt].y, bv.x, bv.y);
                mma_bf16(d[mt][nt], alo[mt].z, ahi[mt].z, alo[mt].w, ahi[mt].w, bv.z, bv.w);
            }
        }
        __syncthreads();
        buf++; if (buf >= 3) buf -= 3;
    }
#undef STAGE_LOAD

    // epilogue: scale by wscale * per-token ascale, write float2
    float ws = g_wscale[wmid];
#pragma unroll
    for (int mt = 0; mt < 4; mt++) {
#pragma unroll
        for (int half = 0; half < 2; half++) {
            int m = m0 + wm + mt * 16 + gid + 8 * half;
            float sc = ws * asc[m];
            float* dst;
            if (mode == 0) {
                int bidx = m >> 11, sidx = m & (SEQ - 1);
                int hh = n0 >> 7;  // 128-wide tiles align with head boundaries
                dst = outp + (((size_t)bidx * nh + hh) * SEQ + sidx) * HD;
            } else {
                dst = outp + (size_t)m * HID + n0;
            }
#pragma unroll
            for (int nt = 0; nt < 8; nt++) {
                int n = wn + nt * 8 + 2 * tig;
                float2 w;
                w.x = d[mt][nt][2 * half] * sc;
                w.y = d[mt][nt][2 * half + 1] * sc;
                *(float2*)(dst + n) = w;
            }
        }
    }
}

// ---------------- causal flash attention, base-2 online softmax, packed f32x2 ----------------
// grid (32 q-tiles [reversed], 32 heads, 2 batch), 256 threads.
// smem: Qs[64][132] | Ks[64][132] (reused as Ps[64][68]) | Vs[64][128]
__global__ __launch_bounds__(256) void k_attn() {
    extern __shared__ float sm[];
    float* Qs = sm;
    float* Ks = sm + 64 * 132;
    float* Ps = Ks;                       // reused after S is computed
    float* Vs = sm + 2 * 64 * 132;
    const int qt = 31 - (int)blockIdx.x;  // heavy tiles first
    const int h = blockIdx.y;
    const int b = blockIdx.z;
    const int tid = threadIdx.x;
    const int tx = tid & 15, ty = tid >> 4;
    const int r0 = ty * 4;

    const float* Qg = g_Q + (((size_t)b * NHEADS + h) * SEQ + (size_t)qt * 64) * HD;
    const float* Kg = g_K + ((size_t)b * NKV + (h >> 2)) * SEQ * HD;
    const float* Vg = g_V + ((size_t)b * NKV + (h >> 2)) * SEQ * HD;

    {   // load Q tile pre-scaled by 1/sqrt(D)
        const float4* Qg4 = (const float4*)Qg;
        for (int i = tid; i < 64 * 32; i += 256) {
            float4 v = Qg4[i];
            v.x *= INV_SQRT_D; v.y *= INV_SQRT_D; v.z *= INV_SQRT_D; v.w *= INV_SQRT_D;
            int row = i >> 5, d4 = i & 31;
            *(float4*)&Qs[row * 132 + d4 * 4] = v;
        }
    }

    float m_i[4], l_i[4];
    unsigned long long o2[4][4];          // O accumulators: 4 rows x 4 d-pairs (8 floats)
#pragma unroll
    for (int i = 0; i < 4; i++) {
        m_i[i] = -1e30f; l_i[i] = 0.f;
#pragma unroll
        for (int p = 0; p < 4; p++) o2[i][p] = 0ull;
    }

    for (int kt = 0; kt <= qt; kt++) {
        __syncthreads();  // previous PV done before overwriting K/V/P
        const float4* Kg4 = (const float4*)(Kg + (size_t)kt * 64 * HD);
        const float4* Vg4 = (const float4*)(Vg + (size_t)kt * 64 * HD);
        for (int i = tid; i < 64 * 32; i += 256) {
            int row = i >> 5, d4 = i & 31;
            *(float4*)&Ks[row * 132 + d4 * 4] = Kg4[i];
            *(float4*)&Vs[row * 128 + d4 * 4] = Vg4[i];
        }
        __syncthreads();

        // ---- S = Q K^T, packed along d (even/odd partial sums per half) ----
        unsigned long long acc2[4][4];
#pragma unroll
        for (int i = 0; i < 4; i++)
#pragma unroll
            for (int j = 0; j < 4; j++) acc2[i][j] = 0ull;
#pragma unroll 4
        for (int d4 = 0; d4 < 32; d4++) {
            unsigned long long aL[4], aH[4], bL[4], bH[4];
#pragma unroll
            for (int i = 0; i < 4; i++) {
                float4 a = *(const float4*)&Qs[(r0 + i) * 132 + d4 * 4];
                aL[i] = pack2(a.x, a.y); aH[i] = pack2(a.z, a.w);
            }
#pragma unroll
            for (int j = 0; j < 4; j++) {
                float4 bb = *(const float4*)&Ks[(j * 16 + tx) * 132 + d4 * 4];
                bL[j] = pack2(bb.x, bb.y); bH[j] = pack2(bb.z, bb.w);
            }
#pragma unroll
            for (int i = 0; i < 4; i++)
#pragma unroll
                for (int j = 0; j < 4; j++) {
                    ffma2(acc2[i][j], aL[i], bL[j]);
                    ffma2(acc2[i][j], aH[i], bH[j]);
                }
        }
        float acc[4][4];
#pragma unroll
        for (int i = 0; i < 4; i++)
#pragma unroll
            for (int j = 0; j < 4; j++) {
                float lo, hi;
                unpack2(acc2[i][j], lo, hi);
                acc[i][j] = lo + hi;
            }
        if (kt == qt) {  // diagonal tile: causal mask
#pragma unroll
            for (int i = 0; i < 4; i++) {
                int rg = qt * 64 + r0 + i;
#pragma unroll
                for (int j = 0; j < 4; j++) {
                    int cg = kt * 64 + j * 16 + tx;
                    if (cg > rg) acc[i][j] = -1e30f;
                }
            }
        }
        __syncthreads();  // all Ks reads done before Ps overwrite

        // ---- online base-2 softmax update ----
#pragma unroll
        for (int i = 0; i < 4; i++) {
            float rm = fmaxf(fmaxf(acc[i][0], acc[i][1]), fmaxf(acc[i][2], acc[i][3]));
#pragma unroll
            for (int o = 8; o > 0; o >>= 1)
                rm = fmaxf(rm, __shfl_xor_sync(0xffffffffu, rm, o, 16));
            float m_new = fmaxf(m_i[i], rm);
            float scale = exp2f(m_i[i] - m_new);
            float p[4], rs = 0.f;
#pragma unroll
            for (int j = 0; j < 4; j++) { p[j] = exp2f(acc[i][j] - m_new); rs += p[j]; }
#pragma unroll
            for (int o = 8; o > 0; o >>= 1)
                rs += __shfl_xor_sync(0xffffffffu, rs, o, 16);
            l_i[i] = l_i[i] * scale + rs;
            m_i[i] = m_new;
            unsigned long long s2 = pack2(scale, scale);
#pragma unroll
            for (int p4 = 0; p4 < 4; p4++) fmul2(o2[i][p4], o2[i][p4], s2);
#pragma unroll
            for (int j = 0; j < 4; j++) Ps[(r0 + i) * 68 + j * 16 + tx] = p[j];
        }
        __syncthreads();  // Ps visible to all

        // ---- O += P V : thread owns d = tx*8..tx*8+7 (4 pairs), packed FMA ----
#pragma unroll 2
        for (int c = 0; c < 64; c++) {
            unsigned long long pv2[4];
#pragma unroll
            for (int i = 0; i < 4; i++) {
                float pv = Ps[(r0 + i) * 68 + c];
                pv2[i] = pack2(pv, pv);
            }
            float4 v0 = *(const float4*)&Vs[c * 128 + tx * 8];
            float4 v1 = *(const float4*)&Vs[c * 128 + tx * 8 + 4];
            unsigned long long vp0 = pack2(v0.x, v0.y), vp1 = pack2(v0.z, v0.w);
            unsigned long long vp2 = pack2(v1.x, v1.y), vp3 = pack2(v1.z, v1.w);
#pragma unroll
            for (int i = 0; i < 4; i++) {
                ffma2(o2[i][0], pv2[i], vp0);
                ffma2(o2[i][1], pv2[i], vp1);
                ffma2(o2[i][2], pv2[i], vp2);
                ffma2(o2[i][3], pv2[i], vp3);
            }
        }
    }

    // ---- normalize + write (token-major into g_attn) ----
#pragma unroll
    for (int i = 0; i < 4; i++) {
        float inv_l = 1.0f / l_i[i];
        int sg = qt * 64 + r0 + i;
        float* dst = g_attn + ((size_t)(b * SEQ + sg)) * HID + h * HD + tx * 8;
        float4 w0, w1;
        unpack2(o2[i][0], w0.x, w0.y);
        unpack2(o2[i][1], w0.z, w0.w);
        unpack2(o2[i][2], w1.x, w1.y);
        unpack2(o2[i][3], w1.z, w1.w);
        w0.x *= inv_l; w0.y *= inv_l; w0.z *= inv_l; w0.w *= inv_l;
        w1.x *= inv_l; w1.y *= inv_l; w1.z *= inv_l; w1.w *= inv_l;
        *(float4*)dst = w0;
        *(float4*)(dst + 4) = w1;
    }
}

// ---------------- launcher ----------------
extern "C" void kernel_launch(void* const* d_in, const int* in_sizes, int n_in,
                              void* d_out, int out_size) {
    const float* hidden = (const float*)d_in[0];
    // d_in[1] is the attention mask: causal additive mask; handled analytically.
    const float* Wq = (const float*)d_in[2];
    const float* Wk = (const float*)d_in[3];
    const float* Wv = (const float*)d_in[4];
    const float* Wo = (const float*)d_in[5];
    float* out = (float*)d_out;

    const int SMEM_ATTN = (2 * 64 * 132 + 64 * 128) * (int)sizeof(float);
    cudaFuncSetAttribute(k_attn, cudaFuncAttributeMaxDynamicSharedMemorySize, SMEM_ATTN);

    // weight scales (mean |W|)
    k_wabs<<<1024, 256>>>(Wq, HID * HID / 4, 0);
    k_wabs<<<1024, 256>>>(Wk, KVDIM * HID / 4, 1);
    k_wabs<<<1024, 256>>>(Wv, KVDIM * HID / 4, 2);
    k_wabs<<<1024, 256>>>(Wo, HID * HID / 4, 3);
    k_wscale<<<4, 256>>>();

    // quantize weights (ternary->bf16) and activations (int8 values->bf16)
    k_quantw<<<dim3(2048, 4), 256>>>(Wq, Wk, Wv, Wo);
    k_actq<<<TOK, 256>>>(hidden, 0);

    // projections (bf16 HMMA tensor cores; exact integer math in bf16/f32)
    k_gemm_hmma<<<dim3(HID / 128, TOK / 128), 128>>>(0, 0, nullptr, NHEADS, 0);   // Q
    k_gemm_hmma<<<dim3(KVDIM / 128, TOK / 128), 128>>>(1, 0, nullptr, NKV, 0);    // K
    k_gemm_hmma<<<dim3(KVDIM / 128, TOK / 128), 128>>>(2, 0, nullptr, NKV, 0);    // V

    // attention
    k_attn<<<dim3(SEQ / 64, NHEADS, BATCH), 256, SMEM_ATTN>>>();

    // output projection
    k_actq<<<TOK, 256>>>(nullptr, 1);
    k_gemm_hmma<<<dim3(HID / 128, TOK / 128), 128>>>(3, 1, out, NHEADS, 1);       // O
}